// round 2
// baseline (speedup 1.0000x reference)
#include <cuda_runtime.h>
#include <cuda_bf16.h>
#include <math.h>

// ---------------------------------------------------------------------------
// Problem constants
// ---------------------------------------------------------------------------
#define BATCH 4
#define SEQ   1024
#define DIM   1024
#define NH    16
#define HS    64
#define NL    4
#define FFD   4096
#define VOCAB 32000
#define ROWS  (BATCH * SEQ)            // 4096 token rows

// ---------------------------------------------------------------------------
// Scratch (static device globals: allowed; runtime alloc is not)
// ---------------------------------------------------------------------------
__device__ float g_x   [(size_t)ROWS * DIM];          // residual stream
__device__ float g_h   [(size_t)ROWS * DIM];          // LN output
__device__ float g_qkv [(size_t)ROWS * 3 * DIM];      // [row][3*1024] q|k|v, head-major inside
__device__ float g_o   [(size_t)ROWS * DIM];          // attn output (b,t,h,s)
__device__ float g_ff  [(size_t)ROWS * FFD];          // MLP hidden
__device__ float g_wp  [(size_t)DIM * 3 * DIM];       // packed Wqkv for one layer
__device__ float g_log [(size_t)ROWS * VOCAB];        // logits (524 MB)
__device__ float g_rl  [ROWS];                        // per-row loss

// ---------------------------------------------------------------------------
// Embedding: x = tok_emb[idx] + pos_emb[t]
// ---------------------------------------------------------------------------
__global__ void embed_kernel(const int* __restrict__ idx,
                             const float* __restrict__ tok,
                             const float* __restrict__ pos,
                             float* __restrict__ x)
{
    int row = blockIdx.x;
    int t   = row & (SEQ - 1);
    int tk  = idx[row];
    const float* te = tok + (size_t)tk * DIM;
    const float* pe = pos + (size_t)t * DIM;
    float* xr = x + (size_t)row * DIM;
    for (int i = threadIdx.x; i < DIM; i += blockDim.x)
        xr[i] = te[i] + pe[i];
}

// ---------------------------------------------------------------------------
// LayerNorm (one block per row of 1024)
// ---------------------------------------------------------------------------
__global__ void ln_kernel(const float* __restrict__ x,
                          const float* __restrict__ g,
                          const float* __restrict__ b,
                          float* __restrict__ y)
{
    int row = blockIdx.x;
    int tid = threadIdx.x;
    const float* xr = x + (size_t)row * DIM;
    float* yr = y + (size_t)row * DIM;

    float s = 0.f, ss = 0.f;
    for (int i = tid; i < DIM; i += 256) {
        float v = xr[i];
        s += v; ss += v * v;
    }
    __shared__ float rs[256], rss[256];
    rs[tid] = s; rss[tid] = ss;
    __syncthreads();
    for (int st = 128; st > 0; st >>= 1) {
        if (tid < st) { rs[tid] += rs[tid + st]; rss[tid] += rss[tid + st]; }
        __syncthreads();
    }
    float mean = rs[0] * (1.0f / DIM);
    float var  = rss[0] * (1.0f / DIM) - mean * mean;
    var = fmaxf(var, 0.f);
    float rstd = rsqrtf(var + 1e-5f);
    for (int i = tid; i < DIM; i += 256)
        yr[i] = (xr[i] - mean) * rstd * g[i] + b[i];
}

// ---------------------------------------------------------------------------
// Pack Wq/Wk/Wv (L,H,D,HS) into [D][3*DIM] row-major for one layer
//   col 0..1023   = q (h*64+s), 1024..2047 = k, 2048..3071 = v
// ---------------------------------------------------------------------------
__global__ void pack_qkv_kernel(const float* __restrict__ Wq,
                                const float* __restrict__ Wk,
                                const float* __restrict__ Wv,
                                float* __restrict__ Wp, int l)
{
    int i = blockIdx.x * 256 + threadIdx.x;          // over DIM*3*DIM
    int d = i / (3 * DIM);
    int c = i % (3 * DIM);
    int which = c >> 10;
    int hc = c & 1023;
    int h = hc >> 6;
    int s = hc & 63;
    const float* W = (which == 0) ? Wq : (which == 1) ? Wk : Wv;
    Wp[i] = W[(((size_t)l * NH + h) * DIM + d) * HS + s];
}

// ---------------------------------------------------------------------------
// SGEMM 128x128x8, 8x8 per thread, 256 threads. Row-major A[MxK], B[KxN].
// EPI: 0 = C=acc+bias   1 = C=res+acc+bias   2 = C=relu(acc+bias)
// M,N multiples of 128; K multiple of 8.
// ---------------------------------------------------------------------------
template <int EPI>
__global__ __launch_bounds__(256)
void sgemm_kernel(const float* __restrict__ A, const float* __restrict__ B,
                  const float* __restrict__ bias, const float* __restrict__ res,
                  float* __restrict__ C, int M, int N, int K)
{
    __shared__ float As[8][128];
    __shared__ float Bs[8][128];
    const int tid = threadIdx.x;
    const int bm = blockIdx.y * 128;
    const int bn = blockIdx.x * 128;

    const int aRow = tid >> 1;
    const int aCol = (tid & 1) << 2;
    const int bRow = tid >> 5;
    const int bCol = (tid & 31) << 2;
    const int ty = (tid >> 4) << 3;
    const int tx = (tid & 15) << 3;

    float acc[8][8];
#pragma unroll
    for (int i = 0; i < 8; i++)
#pragma unroll
        for (int j = 0; j < 8; j++) acc[i][j] = 0.f;

    const float* Ap = A + (size_t)(bm + aRow) * K + aCol;
    const float* Bp = B + (size_t)bRow * N + bn + bCol;

    for (int k0 = 0; k0 < K; k0 += 8) {
        float4 a4 = *(const float4*)(Ap + k0);
        As[aCol + 0][aRow] = a4.x;
        As[aCol + 1][aRow] = a4.y;
        As[aCol + 2][aRow] = a4.z;
        As[aCol + 3][aRow] = a4.w;
        *(float4*)&Bs[bRow][bCol] = *(const float4*)(Bp + (size_t)k0 * N);
        __syncthreads();
#pragma unroll
        for (int k = 0; k < 8; k++) {
            float a[8], b[8];
            *(float4*)(a)     = *(float4*)&As[k][ty];
            *(float4*)(a + 4) = *(float4*)&As[k][ty + 4];
            *(float4*)(b)     = *(float4*)&Bs[k][tx];
            *(float4*)(b + 4) = *(float4*)&Bs[k][tx + 4];
#pragma unroll
            for (int i = 0; i < 8; i++)
#pragma unroll
                for (int j = 0; j < 8; j++)
                    acc[i][j] += a[i] * b[j];
        }
        __syncthreads();
    }

#pragma unroll
    for (int i = 0; i < 8; i++) {
        size_t row = (size_t)(bm + ty + i);
        float* Cr = C + row * N + bn + tx;
        const float* Rr = res ? (res + row * N + bn + tx) : nullptr;
#pragma unroll
        for (int j = 0; j < 8; j++) {
            float v = acc[i][j];
            if (bias) v += bias[bn + tx + j];
            if (EPI == 1) v += Rr[j];
            if (EPI == 2) v = fmaxf(v, 0.f);
            Cr[j] = v;
        }
    }
}

// ---------------------------------------------------------------------------
// Attention scores + causal softmax. One block per (q_row, b*h).
// Writes the [T] probability row (zeros beyond causal) into the attn output.
// ---------------------------------------------------------------------------
__global__ __launch_bounds__(256)
void attn_scores_kernel(const float* __restrict__ qkv, float* __restrict__ attn)
{
    int qt = blockIdx.x;
    int bh = blockIdx.y;            // b*NH + h
    int b  = bh >> 4;
    int hh = bh & 15;
    int tid = threadIdx.x;

    __shared__ float qs[HS];
    __shared__ float row[SEQ];
    __shared__ float red[256];

    const float* qrow = qkv + ((size_t)(b * SEQ + qt)) * (3 * DIM) + hh * HS;
    if (tid < HS) qs[tid] = qrow[tid];
    __syncthreads();

    float lmax = -INFINITY;
    for (int kt = tid; kt <= qt; kt += 256) {
        const float4* k4 = (const float4*)(qkv + ((size_t)(b * SEQ + kt)) * (3 * DIM) + DIM + hh * HS);
        float s = 0.f;
#pragma unroll
        for (int i = 0; i < 16; i++) {
            float4 kv = k4[i];
            s += qs[4 * i] * kv.x + qs[4 * i + 1] * kv.y
               + qs[4 * i + 2] * kv.z + qs[4 * i + 3] * kv.w;
        }
        s *= 0.125f;                 // HS^-0.5
        row[kt] = s;
        lmax = fmaxf(lmax, s);
    }
    red[tid] = lmax;
    __syncthreads();
    for (int st = 128; st > 0; st >>= 1) {
        if (tid < st) red[tid] = fmaxf(red[tid], red[tid + st]);
        __syncthreads();
    }
    float m = red[0];
    __syncthreads();

    float lsum = 0.f;
    for (int kt = tid; kt <= qt; kt += 256) {
        float e = expf(row[kt] - m);
        row[kt] = e;
        lsum += e;
    }
    red[tid] = lsum;
    __syncthreads();
    for (int st = 128; st > 0; st >>= 1) {
        if (tid < st) red[tid] += red[tid + st];
        __syncthreads();
    }
    float inv = 1.0f / red[0];

    float* dst = attn + ((size_t)bh * SEQ + qt) * SEQ;
    for (int kt = tid; kt < SEQ; kt += 256)
        dst[kt] = (kt <= qt) ? row[kt] * inv : 0.f;
}

// ---------------------------------------------------------------------------
// o[b,t,h,s] = sum_k wei[b,h,t,k] * v[b,h,k,s]. One block per (q_row, b*h).
// ---------------------------------------------------------------------------
__global__ __launch_bounds__(256)
void attn_av_kernel(const float* __restrict__ qkv, const float* __restrict__ attn,
                    float* __restrict__ o)
{
    int qt = blockIdx.x;
    int bh = blockIdx.y;
    int b  = bh >> 4;
    int hh = bh & 15;
    int tid = threadIdx.x;

    __shared__ float w[SEQ];
    __shared__ float part[4][HS];

    const float* wrow = attn + ((size_t)bh * SEQ + qt) * SEQ;
    for (int i = tid; i <= qt; i += 256) w[i] = wrow[i];
    __syncthreads();

    int s   = tid & 63;
    int grp = tid >> 6;
    float acc = 0.f;
    for (int kt = grp; kt <= qt; kt += 4)
        acc += w[kt] * qkv[((size_t)(b * SEQ + kt)) * (3 * DIM) + 2 * DIM + hh * HS + s];
    part[grp][s] = acc;
    __syncthreads();
    if (tid < HS) {
        float t = part[0][tid] + part[1][tid] + part[2][tid] + part[3][tid];
        o[((size_t)(b * SEQ + qt)) * DIM + hh * HS + tid] = t;
    }
}

// ---------------------------------------------------------------------------
// Per-row NLL with online logsumexp over vocab. One block per token row.
// ---------------------------------------------------------------------------
__global__ __launch_bounds__(256)
void loss_rows_kernel(const float* __restrict__ logits,
                      const int* __restrict__ targets,
                      float* __restrict__ rowloss)
{
    int row = blockIdx.x;
    int tid = threadIdx.x;
    const float* lr = logits + (size_t)row * VOCAB;

    float m = -INFINITY, s = 0.f;
    for (int v = tid; v < VOCAB; v += 256) {
        float z = lr[v];
        if (z > m) { s = s * expf(m - z) + 1.f; m = z; }
        else        s += expf(z - m);
    }
    __shared__ float ms[256], ss[256];
    ms[tid] = m; ss[tid] = s;
    __syncthreads();
    for (int st = 128; st > 0; st >>= 1) {
        if (tid < st) {
            float m2 = ms[tid + st], s2 = ss[tid + st];
            float M = fmaxf(ms[tid], m2);
            ss[tid] = ss[tid] * expf(ms[tid] - M) + s2 * expf(m2 - M);
            ms[tid] = M;
        }
        __syncthreads();
    }
    if (tid == 0) {
        float zt = lr[targets[row]];
        rowloss[row] = ms[0] + logf(ss[0]) - zt;
    }
}

__global__ void loss_reduce_kernel(const float* __restrict__ rowloss, float* __restrict__ out)
{
    __shared__ float red[256];
    int tid = threadIdx.x;
    float s = 0.f;
    for (int i = tid; i < ROWS; i += 256) s += rowloss[i];
    red[tid] = s;
    __syncthreads();
    for (int st = 128; st > 0; st >>= 1) {
        if (tid < st) red[tid] += red[tid + st];
        __syncthreads();
    }
    if (tid == 0) out[0] = red[0] * (1.0f / ROWS);
}

// ---------------------------------------------------------------------------
// Launch
// ---------------------------------------------------------------------------
extern "C" void kernel_launch(void* const* d_in, const int* in_sizes, int n_in,
                              void* d_out, int out_size)
{
    const int*   idx     = (const int*)  d_in[0];
    const int*   targets = (const int*)  d_in[1];
    const float* tok_emb = (const float*)d_in[2];
    const float* pos_emb = (const float*)d_in[3];
    const float* ln1_g   = (const float*)d_in[4];
    const float* ln1_b   = (const float*)d_in[5];
    const float* Wq      = (const float*)d_in[6];
    const float* Wk      = (const float*)d_in[7];
    const float* Wv      = (const float*)d_in[8];
    const float* Wp      = (const float*)d_in[9];
    const float* bp      = (const float*)d_in[10];
    const float* ln2_g   = (const float*)d_in[11];
    const float* ln2_b   = (const float*)d_in[12];
    const float* W1      = (const float*)d_in[13];
    const float* b1      = (const float*)d_in[14];
    const float* W2      = (const float*)d_in[15];
    const float* b2      = (const float*)d_in[16];
    const float* lnf_g   = (const float*)d_in[17];
    const float* lnf_b   = (const float*)d_in[18];
    const float* Wlm     = (const float*)d_in[19];
    const float* blm     = (const float*)d_in[20];

    float* out      = (float*)d_out;
    float* attn_out = out + 1;            // [L,B,H,T,T] after the scalar loss

    float *x, *h, *qkv, *o, *ff, *wp, *lg, *rl;
    cudaGetSymbolAddress((void**)&x,  g_x);
    cudaGetSymbolAddress((void**)&h,  g_h);
    cudaGetSymbolAddress((void**)&qkv,g_qkv);
    cudaGetSymbolAddress((void**)&o,  g_o);
    cudaGetSymbolAddress((void**)&ff, g_ff);
    cudaGetSymbolAddress((void**)&wp, g_wp);
    cudaGetSymbolAddress((void**)&lg, g_log);
    cudaGetSymbolAddress((void**)&rl, g_rl);

    embed_kernel<<<ROWS, 256>>>(idx, tok_emb, pos_emb, x);

    for (int l = 0; l < NL; l++) {
        // LN1
        ln_kernel<<<ROWS, 256>>>(x, ln1_g + (size_t)l * DIM, ln1_b + (size_t)l * DIM, h);
        // pack Wq|Wk|Wv into [D][3D]
        pack_qkv_kernel<<<(DIM * 3 * DIM) / 256, 256>>>(Wq, Wk, Wv, wp, l);
        // qkv = h @ Wpack
        sgemm_kernel<0><<<dim3(3 * DIM / 128, ROWS / 128), 256>>>(
            h, wp, nullptr, nullptr, qkv, ROWS, 3 * DIM, DIM);
        // scores + softmax -> attn output region (also the spec'd output)
        float* attnL = attn_out + (size_t)l * BATCH * NH * SEQ * SEQ;
        attn_scores_kernel<<<dim3(SEQ, BATCH * NH), 256>>>(qkv, attnL);
        // o = wei @ v
        attn_av_kernel<<<dim3(SEQ, BATCH * NH), 256>>>(qkv, attnL, o);
        // x = x + o @ Wp + bp
        sgemm_kernel<1><<<dim3(DIM / 128, ROWS / 128), 256>>>(
            o, Wp + (size_t)l * DIM * DIM, bp + (size_t)l * DIM, x, x, ROWS, DIM, DIM);
        // LN2
        ln_kernel<<<ROWS, 256>>>(x, ln2_g + (size_t)l * DIM, ln2_b + (size_t)l * DIM, h);
        // ff = relu(h @ W1 + b1)
        sgemm_kernel<2><<<dim3(FFD / 128, ROWS / 128), 256>>>(
            h, W1 + (size_t)l * DIM * FFD, b1 + (size_t)l * FFD, nullptr, ff, ROWS, FFD, DIM);
        // x = x + ff @ W2 + b2
        sgemm_kernel<1><<<dim3(DIM / 128, ROWS / 128), 256>>>(
            ff, W2 + (size_t)l * FFD * DIM, b2 + (size_t)l * DIM, x, x, ROWS, DIM, FFD);
    }

    // final LN + LM head
    ln_kernel<<<ROWS, 256>>>(x, lnf_g, lnf_b, h);
    sgemm_kernel<0><<<dim3(VOCAB / 128, ROWS / 128), 256>>>(
        h, Wlm, blm, nullptr, lg, ROWS, VOCAB, DIM);

    // loss
    loss_rows_kernel<<<ROWS, 256>>>(lg, targets, rl);
    loss_reduce_kernel<<<1, 256>>>(rl, out);
}